// round 16
// baseline (speedup 1.0000x reference)
#include <cuda_runtime.h>

#define NB   512
#define NC   16
#define NT   2000
#define NRES 1024
#define NCLS 10
#define NBLK 148
#define NTHR 512
#define ALPHA 0.9f

#define CHK   128                    // k per chunk
#define NCHK  (NRES / CHK)           // 8 chunks per step
#define CHKB  (CHK * 128 * 4)        // 65536 B per chunk buffer

// Dynamic smem layout (bytes):
//   [0, 2*CHKB)            Bs double buffer
//   [2*CHKB, +4096)        sMask 32x32 u32
//   [.., +2048)            sx 32x16 f32
//   [.., +8704)            sWin 128x17 f32
//   [.., +16)              mbarriers x2
#define OFF_MASK (2 * CHKB)
#define OFF_SX   (OFF_MASK + 4096)
#define OFF_WIN  (OFF_SX + 2048)
#define OFF_MBAR (OFF_WIN + 8704)
#define SMEM_TOTAL (OFF_MBAR + 16)

// Persistent cross-CTA state.
__device__ float g_s[2][NB * NRES];            // spikes, [b][j] (classifier)
__device__ unsigned g_mask[2][NB][32];         // spike bitmask: bit i of word w = neuron 32w+i
__device__ float g_W2[NRES * NRES];            // Wres^T repacked: [j_tile][kc][k][j_local], 64KB blocks
__device__ float g_xT[(size_t)NT * NB * NC];   // x^T: [t][b][c]
__device__ unsigned g_bar_count;
__device__ unsigned g_bar_gen;

static __device__ __forceinline__ unsigned ld_acq(const unsigned* p) {
    unsigned v;
    asm volatile("ld.acquire.gpu.global.u32 %0, [%1];" : "=r"(v) : "l"(p) : "memory");
    return v;
}
static __device__ __forceinline__ void st_rel(unsigned* p, unsigned v) {
    asm volatile("st.release.gpu.global.u32 [%0], %1;" :: "l"(p), "r"(v) : "memory");
}

// Grid-wide barrier; all 148 CTAs resident (1 per SM).
static __device__ __forceinline__ void grid_barrier() {
    __syncthreads();
    if (threadIdx.x == 0) {
        unsigned gen = ld_acq(&g_bar_gen);
        __threadfence();
        if (atomicAdd(&g_bar_count, 1u) == NBLK - 1u) {
            g_bar_count = 0u;
            __threadfence();
            st_rel(&g_bar_gen, gen + 1u);
        } else {
            while (ld_acq(&g_bar_gen) == gen) { }
        }
    }
    __syncthreads();
}

static __device__ __forceinline__ unsigned long long pack2(float lo, float hi) {
    unsigned long long r;
    asm("mov.b64 %0, {%1, %2};" : "=l"(r) : "f"(lo), "f"(hi));
    return r;
}
static __device__ __forceinline__ void unpack2(unsigned long long p, float& lo, float& hi) {
    asm("mov.b64 {%0, %1}, %2;" : "=f"(lo), "=f"(hi) : "l"(p));
}
// add.rn.f32x2: two independent rn fp32 adds — per-lane bit-identical to __fadd_rn.
static __device__ __forceinline__ unsigned long long add2(unsigned long long a,
                                                          unsigned long long b) {
    unsigned long long r;
    asm("add.rn.f32x2 %0, %1, %2;" : "=l"(r) : "l"(a), "l"(b));
    return r;
}

// ---- bulk-async (TMA 1D) staging ----
static __device__ __forceinline__ void mbar_init(unsigned mbar, unsigned count) {
    asm volatile("mbarrier.init.shared.b64 [%0], %1;" :: "r"(mbar), "r"(count) : "memory");
}
static __device__ __forceinline__ void mbar_expect_tx(unsigned mbar, unsigned bytes) {
    asm volatile("mbarrier.arrive.expect_tx.shared.b64 _, [%0], %1;"
                 :: "r"(mbar), "r"(bytes) : "memory");
}
static __device__ __forceinline__ void mbar_wait(unsigned mbar, unsigned parity) {
    asm volatile(
        "{\n\t.reg .pred p;\n\t"
        "WAIT_%=:\n\t"
        "mbarrier.try_wait.parity.acquire.cta.shared::cta.b64 p, [%0], %1;\n\t"
        "@!p bra WAIT_%=;\n\t"
        "}" :: "r"(mbar), "r"(parity) : "memory");
}
static __device__ __forceinline__ void bulk_g2s(unsigned dst, const void* src,
                                                unsigned bytes, unsigned mbar) {
    asm volatile(
        "cp.async.bulk.shared::cluster.global.mbarrier::complete_tx::bytes "
        "[%0], [%1], %2, [%3];"
        :: "r"(dst), "l"(src), "r"(bytes), "r"(mbar) : "memory");
}

__global__ __launch_bounds__(NTHR, 1) void reservoir_persistent(
    const float* __restrict__ x,     // (NB, NC, NT)
    const float* __restrict__ Win,   // (NRES, NC)
    const float* __restrict__ Wres,  // (NRES, NRES)
    const float* __restrict__ Wclf,  // (NCLS, NRES)
    float* __restrict__ out)         // [NB*NCLS | NB*NRES]
{
    extern __shared__ __align__(128) char smem[];
    const int blk = blockIdx.x;
    const int tid = threadIdx.x;

    float* Bs = (float*)smem;
    unsigned (*sMask)[32] = (unsigned(*)[32])(smem + OFF_MASK);
    float (*sx)[16]   = (float(*)[16])(smem + OFF_SX);
    float (*sWin)[17] = (float(*)[17])(smem + OFF_WIN);

    // ---- Phase 0 (all CTAs): one-time repack/transpose + mask zero ----
    {
        const int g0 = blk * NTHR + tid;
        const int gs = NBLK * NTHR;
        for (int i = g0; i < NRES * NRES; i += gs) {
            int j = i >> 10, k = i & (NRES - 1);
            // block = [j>>7][k>>7], 16384 floats each; inside: [k&127][j&127]
            g_W2[(((j >> 7) * NCHK + (k >> 7)) << 14) + ((k & 127) << 7) + (j & 127)] = Wres[i];
        }
        for (size_t i = g0; i < (size_t)NT * NB * NC; i += (size_t)gs) {
            int t = (int)(i >> 13);
            int r = (int)(i & 8191);
            int b = r >> 4, c = r & 15;
            g_xT[i] = x[((size_t)(b * NC + c)) * NT + t];
        }
        for (int i = g0; i < NB * 32; i += gs)
            ((unsigned*)g_mask[0])[i] = 0u;
    }

    if (blk < 128) {
        // ------------- Reservoir path: CTA = 32 b x 128 j -------------------
        const int b0 = (blk >> 3) * 32;      // 16 b-tiles
        const int j0 = (blk & 7) * 128;      // 8 j-tiles
        const int jt = blk & 7;

        const int w    = tid >> 5;           // warp 0..15 -> rows w*2, w*2+1
        const int lane = tid & 31;           // lane -> cols lane*4 .. lane*4+3
        const int rl0 = w * 2;
        const int cl0 = lane * 4;

        const unsigned bs_u    = (unsigned)__cvta_generic_to_shared(Bs);
        const unsigned mask_u  = bs_u + OFF_MASK;
        const unsigned sx_u    = bs_u + OFF_SX;
        const unsigned mbar0_u = bs_u + OFF_MBAR;
        const unsigned mbar1_u = bs_u + OFF_MBAR + 8;

        if (tid == 0) {
            mbar_init(mbar0_u, 1);
            mbar_init(mbar1_u, 1);
        }

        // Zero step-0 float spikes.
        {
            float4 z = make_float4(0.f, 0.f, 0.f, 0.f);
#pragma unroll
            for (int i = 0; i < 2; i++)
                *(float4*)&g_s[0][(size_t)(b0 + rl0 + i) * NRES + j0 + cl0] = z;
        }
        for (int e = tid; e < 128 * 16; e += NTHR) {
            int r = e >> 4, c = e & 15;
            sWin[r][c] = Win[(size_t)(j0 + r) * NC + c];
        }

        float v[8], cnt[8];
#pragma unroll
        for (int q = 0; q < 8; q++) { v[q] = 0.f; cnt[q] = 0.f; }

        unsigned ph[2] = {0u, 0u};

        grid_barrier();   // mbarrier init + g_W2 globally visible

        for (int t = 0; t < NT; ++t) {
            float* __restrict__ s_next = g_s[(t + 1) & 1];
            const int buf  = t & 1;
            const int nbuf = (t + 1) & 1;

            // Prologue: bulk-stage chunk 7 (k 896..1023) + masks + x_t on mbar1.
            if (tid == 0) {
                mbar_expect_tx(mbar1_u, (unsigned)CHKB + 4096u + 2048u);
                bulk_g2s(bs_u + (unsigned)CHKB,
                         &g_W2[(size_t)(jt * NCHK + (NCHK - 1)) << 14],
                         (unsigned)CHKB, mbar1_u);
                bulk_g2s(mask_u, &g_mask[buf][b0][0], 4096u, mbar1_u);
                bulk_g2s(sx_u, &g_xT[(size_t)t * (NB * NC) + (size_t)b0 * NC], 2048u, mbar1_u);
            }

            // acc2[bb][h]: b row bb, j pair h (4 j per lane).
            unsigned long long acc2[2][2];
#pragma unroll
            for (int i = 0; i < 2; i++) {
                acc2[i][0] = pack2(0.f, 0.f);
                acc2[i][1] = pack2(0.f, 0.f);
            }

            for (int kc = NCHK - 1; kc >= 0; --kc) {
                const int pb = kc & 1;
                if (tid == 0 && kc > 0) {
                    const unsigned m = (kc & 1) ? mbar0_u : mbar1_u;   // (kc-1)&1
                    mbar_expect_tx(m, (unsigned)CHKB);
                    bulk_g2s(bs_u + (unsigned)((kc - 1) & 1) * (unsigned)CHKB,
                             &g_W2[(size_t)(jt * NCHK + (kc - 1)) << 14],
                             (unsigned)CHKB, m);
                }

                mbar_wait(pb ? mbar1_u : mbar0_u, ph[pb]);

                const unsigned bbase = bs_u + (unsigned)pb * (unsigned)CHKB
                                       + (unsigned)cl0 * 4;
                // Sparse ordered accumulation, bit-exact: chunks descending,
                // words descending (wd 3..0), bits high->low = k descending.
#pragma unroll
                for (int bb = 0; bb < 2; ++bb) {
                    unsigned long long a0 = acc2[bb][0];
                    unsigned long long a1 = acc2[bb][1];
#pragma unroll
                    for (int wd = 3; wd >= 0; --wd) {
                        unsigned m = sMask[rl0 + bb][kc * 4 + wd];   // warp-uniform
                        const unsigned wbase = bbase + (unsigned)(wd * 32) * 512u;
                        while (m) {
                            int k = 31 - __clz(m);
                            m &= ~(1u << k);
                            unsigned long long w01, w23;
                            asm("ld.shared.v2.u64 {%0, %1}, [%2];"
                                : "=l"(w01), "=l"(w23)
                                : "r"(wbase + (unsigned)k * 512));
                            a0 = add2(a0, w01);
                            a1 = add2(a1, w23);
                        }
                    }
                    acc2[bb][0] = a0;
                    acc2[bb][1] = a1;
                }
                ph[pb] ^= 1u;
                __syncthreads();   // all readers done with buffer pb
            }

            // Epilogue (frozen): vn = rn(fma(0.9, v, d_in) + d_rec)
#pragma unroll
            for (int i = 0; i < 2; i++) {
                const int rb = rl0 + i;
                float d[4] = {0.f, 0.f, 0.f, 0.f};
#pragma unroll
                for (int c = 0; c < NC; c++) {
                    float xv = sx[rb][c];
#pragma unroll
                    for (int j = 0; j < 4; j++)
                        d[j] = __fmaf_rn(xv, sWin[cl0 + j][c], d[j]);
                }
                float r01[2], r23[2];
                unpack2(acc2[i][0], r01[0], r01[1]);
                unpack2(acc2[i][1], r23[0], r23[1]);
                float rr[4] = {r01[0], r01[1], r23[0], r23[1]};
                float sp[4];
                unsigned bits = 0;
#pragma unroll
                for (int j = 0; j < 4; j++) {
                    float vn = __fadd_rn(__fmaf_rn(ALPHA, v[i * 4 + j], d[j]), rr[j]);
                    float s = (vn >= 1.0f) ? 1.0f : 0.0f;
                    v[i * 4 + j] = (vn >= 1.0f) ? 0.0f : vn;
                    cnt[i * 4 + j] += s;
                    sp[j] = s;
                    bits |= (s != 0.f) ? (1u << j) : 0u;
                }
                *(float4*)&s_next[(size_t)(b0 + rb) * NRES + j0 + cl0] =
                    make_float4(sp[0], sp[1], sp[2], sp[3]);

                unsigned partial = bits << (cl0 & 31);
                unsigned grp = 0xFFu << ((lane >> 3) << 3);
                unsigned word = __reduce_or_sync(grp, partial);
                if ((lane & 7) == 0)
                    g_mask[nbuf][b0 + rb][(j0 >> 5) + (lane >> 3)] = word;
            }

            grid_barrier();
        }
        grid_barrier();   // classifier finishes step NT-1

#pragma unroll
        for (int i = 0; i < 2; i++) {
            *(float4*)&out[(size_t)NB * NCLS +
                           (size_t)(b0 + rl0 + i) * NRES + j0 + cl0] =
                make_float4(cnt[i * 4 + 0], cnt[i * 4 + 1],
                            cnt[i * 4 + 2], cnt[i * 4 + 3]);
        }
    } else {
        // ---------------- Classifier path (tid<256 active; numerics frozen) --
        const bool active = tid < 256;
        const int idx = (blk - 128) * 256 + tid;
        const int b = idx / NCLS;
        const int m = idx % NCLS;
        float vc = 0.f, cc = 0.f;

        grid_barrier();

        for (int t = 0; t <= NT; ++t) {
            if (t >= 1 && active) {
                const float* __restrict__ s_prev = g_s[t & 1];
                const float* srow = &s_prev[(size_t)b * NRES];
                const float* wrow = &Wclf[(size_t)m * NRES];
                float tot = 0.f;
#pragma unroll
                for (int blkk = 0; blkk < 4; ++blkk) {
                    float a = 0.f;
#pragma unroll 8
                    for (int n = 0; n < 256; n += 4) {
                        int base = blkk * 256 + n;
                        float4 sv = __ldcg((const float4*)(srow + base));
                        float4 wv = *(const float4*)(wrow + base);
                        a = __fmaf_rn(sv.x, wv.x, a);
                        a = __fmaf_rn(sv.y, wv.y, a);
                        a = __fmaf_rn(sv.z, wv.z, a);
                        a = __fmaf_rn(sv.w, wv.w, a);
                    }
                    tot = __fadd_rn(tot, a);
                }
                float vn = __fmaf_rn(ALPHA, vc, tot);
                float s = (vn >= 1.0f) ? 1.0f : 0.0f;
                vc = (vn >= 1.0f) ? 0.0f : vn;
                cc += s;
            }
            grid_barrier();
        }
        if (active) out[idx] = cc;
    }
}

extern "C" void kernel_launch(void* const* d_in, const int* in_sizes, int n_in,
                              void* d_out, int out_size) {
    const float* x = 0; const float* Win = 0;
    const float* Wres = 0; const float* Wclf = 0;
    for (int i = 0; i < n_in; ++i) {
        switch (in_sizes[i]) {
            case NB * NC * NT:   x    = (const float*)d_in[i]; break;
            case NRES * NC:      Win  = (const float*)d_in[i]; break;
            case NRES * NRES:    Wres = (const float*)d_in[i]; break;
            case NCLS * NRES:    Wclf = (const float*)d_in[i]; break;
        }
    }
    float* out = (float*)d_out;

    cudaFuncSetAttribute(reservoir_persistent,
                         cudaFuncAttributeMaxDynamicSharedMemorySize, SMEM_TOTAL);
    reservoir_persistent<<<NBLK, NTHR, SMEM_TOTAL>>>(x, Win, Wres, Wclf, out);
}

// round 17
// speedup vs baseline: 1.0007x; 1.0007x over previous
#include <cuda_runtime.h>

#define NB   512
#define NC   16
#define NT   2000
#define NRES 1024
#define NCLS 10
#define NBLK 148
#define NTHR 512
#define ALPHA 0.9f

#define CHK   128
#define NCHK  (NRES / CHK)
#define CHKB  (CHK * 128 * 4)

#define OFF_MASK (2 * CHKB)
#define OFF_SX   (OFF_MASK + 4096)
#define OFF_WIN  (OFF_SX + 2048)
#define OFF_MBAR (OFF_WIN + 8704)
#define SMEM_TOTAL (OFF_MBAR + 16)

__device__ float g_s[2][NB * NRES];
__device__ unsigned g_mask[2][NB][32];
__device__ float g_W2[NRES * NRES];            // [j_tile][kc][k][j_local], 64KB blocks
__device__ float g_xT[(size_t)NT * NB * NC];
__device__ unsigned g_bar_count;
__device__ unsigned g_bar_gen;

static __device__ __forceinline__ unsigned ld_acq(const unsigned* p) {
    unsigned v;
    asm volatile("ld.acquire.gpu.global.u32 %0, [%1];" : "=r"(v) : "l"(p) : "memory");
    return v;
}
static __device__ __forceinline__ void st_rel(unsigned* p, unsigned v) {
    asm volatile("st.release.gpu.global.u32 [%0], %1;" :: "l"(p), "r"(v) : "memory");
}

static __device__ __forceinline__ void grid_barrier() {
    __syncthreads();
    if (threadIdx.x == 0) {
        unsigned gen = ld_acq(&g_bar_gen);
        __threadfence();
        if (atomicAdd(&g_bar_count, 1u) == NBLK - 1u) {
            g_bar_count = 0u;
            __threadfence();
            st_rel(&g_bar_gen, gen + 1u);
        } else {
            while (ld_acq(&g_bar_gen) == gen) { }
        }
    }
    __syncthreads();
}

static __device__ __forceinline__ unsigned long long pack2(float lo, float hi) {
    unsigned long long r;
    asm("mov.b64 %0, {%1, %2};" : "=l"(r) : "f"(lo), "f"(hi));
    return r;
}
static __device__ __forceinline__ void unpack2(unsigned long long p, float& lo, float& hi) {
    asm("mov.b64 {%0, %1}, %2;" : "=f"(lo), "=f"(hi) : "l"(p));
}
static __device__ __forceinline__ unsigned long long add2(unsigned long long a,
                                                          unsigned long long b) {
    unsigned long long r;
    asm("add.rn.f32x2 %0, %1, %2;" : "=l"(r) : "l"(a), "l"(b));
    return r;
}
static __device__ __forceinline__ void lds_v2u64(unsigned long long& a,
                                                 unsigned long long& b, unsigned addr) {
    asm volatile("ld.shared.v2.u64 {%0, %1}, [%2];" : "=l"(a), "=l"(b) : "r"(addr));
}

static __device__ __forceinline__ void mbar_init(unsigned mbar, unsigned count) {
    asm volatile("mbarrier.init.shared.b64 [%0], %1;" :: "r"(mbar), "r"(count) : "memory");
}
static __device__ __forceinline__ void mbar_expect_tx(unsigned mbar, unsigned bytes) {
    asm volatile("mbarrier.arrive.expect_tx.shared.b64 _, [%0], %1;"
                 :: "r"(mbar), "r"(bytes) : "memory");
}
static __device__ __forceinline__ void mbar_wait(unsigned mbar, unsigned parity) {
    asm volatile(
        "{\n\t.reg .pred p;\n\t"
        "WAIT_%=:\n\t"
        "mbarrier.try_wait.parity.acquire.cta.shared::cta.b64 p, [%0], %1;\n\t"
        "@!p bra WAIT_%=;\n\t"
        "}" :: "r"(mbar), "r"(parity) : "memory");
}
static __device__ __forceinline__ void bulk_g2s(unsigned dst, const void* src,
                                                unsigned bytes, unsigned mbar) {
    asm volatile(
        "cp.async.bulk.shared::cluster.global.mbarrier::complete_tx::bytes "
        "[%0], [%1], %2, [%3];"
        :: "r"(dst), "l"(src), "r"(bytes), "r"(mbar) : "memory");
}

__global__ __launch_bounds__(NTHR, 1) void reservoir_persistent(
    const float* __restrict__ x,
    const float* __restrict__ Win,
    const float* __restrict__ Wres,
    const float* __restrict__ Wclf,
    float* __restrict__ out)
{
    extern __shared__ __align__(128) char smem[];
    const int blk = blockIdx.x;
    const int tid = threadIdx.x;

    float* Bs = (float*)smem;
    unsigned (*sMask)[32] = (unsigned(*)[32])(smem + OFF_MASK);
    float (*sx)[16]   = (float(*)[16])(smem + OFF_SX);
    float (*sWin)[17] = (float(*)[17])(smem + OFF_WIN);

    // ---- Phase 0: one-time repack/transpose + mask zero ----
    {
        const int g0 = blk * NTHR + tid;
        const int gs = NBLK * NTHR;
        for (int i = g0; i < NRES * NRES; i += gs) {
            int j = i >> 10, k = i & (NRES - 1);
            g_W2[(((j >> 7) * NCHK + (k >> 7)) << 14) + ((k & 127) << 7) + (j & 127)] = Wres[i];
        }
        for (size_t i = g0; i < (size_t)NT * NB * NC; i += (size_t)gs) {
            int t = (int)(i >> 13);
            int r = (int)(i & 8191);
            int b = r >> 4, c = r & 15;
            g_xT[i] = x[((size_t)(b * NC + c)) * NT + t];
        }
        for (int i = g0; i < NB * 32; i += gs)
            ((unsigned*)g_mask[0])[i] = 0u;
    }

    if (blk < 128) {
        const int b0 = (blk >> 3) * 32;
        const int j0 = (blk & 7) * 128;
        const int jt = blk & 7;

        const int w    = tid >> 5;
        const int lane = tid & 31;
        const int rl0 = w * 2;
        const int cl0 = lane * 4;

        const unsigned bs_u    = (unsigned)__cvta_generic_to_shared(Bs);
        const unsigned mask_u  = bs_u + OFF_MASK;
        const unsigned sx_u    = bs_u + OFF_SX;
        const unsigned mbar0_u = bs_u + OFF_MBAR;
        const unsigned mbar1_u = bs_u + OFF_MBAR + 8;

        if (tid == 0) {
            mbar_init(mbar0_u, 1);
            mbar_init(mbar1_u, 1);
        }

        {
            float4 z = make_float4(0.f, 0.f, 0.f, 0.f);
#pragma unroll
            for (int i = 0; i < 2; i++)
                *(float4*)&g_s[0][(size_t)(b0 + rl0 + i) * NRES + j0 + cl0] = z;
        }
        for (int e = tid; e < 128 * 16; e += NTHR) {
            int r = e >> 4, c = e & 15;
            sWin[r][c] = Win[(size_t)(j0 + r) * NC + c];
        }

        float v[8], cnt[8];
#pragma unroll
        for (int q = 0; q < 8; q++) { v[q] = 0.f; cnt[q] = 0.f; }

        unsigned ph[2] = {0u, 0u};

        grid_barrier();

        for (int t = 0; t < NT; ++t) {
            float* __restrict__ s_next = g_s[(t + 1) & 1];
            const int buf  = t & 1;
            const int nbuf = (t + 1) & 1;

            if (tid == 0) {
                mbar_expect_tx(mbar1_u, (unsigned)CHKB + 4096u + 2048u);
                bulk_g2s(bs_u + (unsigned)CHKB,
                         &g_W2[(size_t)(jt * NCHK + (NCHK - 1)) << 14],
                         (unsigned)CHKB, mbar1_u);
                bulk_g2s(mask_u, &g_mask[buf][b0][0], 4096u, mbar1_u);
                bulk_g2s(sx_u, &g_xT[(size_t)t * (NB * NC) + (size_t)b0 * NC], 2048u, mbar1_u);
            }

            unsigned long long a00 = pack2(0.f, 0.f), a01 = a00, a10 = a00, a11 = a00;

            for (int kc = NCHK - 1; kc >= 0; --kc) {
                const int pb = kc & 1;
                if (tid == 0 && kc > 0) {
                    const unsigned m = (kc & 1) ? mbar0_u : mbar1_u;
                    mbar_expect_tx(m, (unsigned)CHKB);
                    bulk_g2s(bs_u + (unsigned)((kc - 1) & 1) * (unsigned)CHKB,
                             &g_W2[(size_t)(jt * NCHK + (kc - 1)) << 14],
                             (unsigned)CHKB, m);
                }

                mbar_wait(pb ? mbar1_u : mbar0_u, ph[pb]);

                const unsigned bbase = bs_u + (unsigned)pb * (unsigned)CHKB
                                       + (unsigned)cl0 * 4;

                // Dual-b, one-ahead pipelined sparse walk. Masks are
                // warp-uniform -> uniform branches. Per-b add order is the
                // exact frozen descending-k chain (bit-identical).
#pragma unroll
                for (int wd = 3; wd >= 0; --wd) {
                    unsigned mA = sMask[rl0 + 0][kc * 4 + wd];
                    unsigned mB = sMask[rl0 + 1][kc * 4 + wd];
                    const unsigned wb = bbase + (unsigned)(wd * 32) * 512u;

                    unsigned long long pA0, pA1, pB0, pB1;
                    bool vA = (mA != 0u), vB = (mB != 0u);
                    if (vA) {
                        int k = 31 - __clz(mA); mA &= ~(1u << k);
                        lds_v2u64(pA0, pA1, wb + (unsigned)k * 512u);
                    }
                    if (vB) {
                        int k = 31 - __clz(mB); mB &= ~(1u << k);
                        lds_v2u64(pB0, pB1, wb + (unsigned)k * 512u);
                    }
                    while (vA | vB) {
                        unsigned long long nA0, nA1, nB0, nB1;
                        bool nvA = (mA != 0u), nvB = (mB != 0u);
                        if (nvA) {
                            int k = 31 - __clz(mA); mA &= ~(1u << k);
                            lds_v2u64(nA0, nA1, wb + (unsigned)k * 512u);
                        }
                        if (nvB) {
                            int k = 31 - __clz(mB); mB &= ~(1u << k);
                            lds_v2u64(nB0, nB1, wb + (unsigned)k * 512u);
                        }
                        if (vA) { a00 = add2(a00, pA0); a01 = add2(a01, pA1); }
                        if (vB) { a10 = add2(a10, pB0); a11 = add2(a11, pB1); }
                        pA0 = nA0; pA1 = nA1; pB0 = nB0; pB1 = nB1;
                        vA = nvA; vB = nvB;
                    }
                }
                ph[pb] ^= 1u;
                __syncthreads();
            }

            unsigned long long acc2[2][2] = {{a00, a01}, {a10, a11}};

            // Epilogue (frozen): vn = rn(fma(0.9, v, d_in) + d_rec)
#pragma unroll
            for (int i = 0; i < 2; i++) {
                const int rb = rl0 + i;
                float d[4] = {0.f, 0.f, 0.f, 0.f};
#pragma unroll
                for (int c = 0; c < NC; c++) {
                    float xv = sx[rb][c];
#pragma unroll
                    for (int j = 0; j < 4; j++)
                        d[j] = __fmaf_rn(xv, sWin[cl0 + j][c], d[j]);
                }
                float r01[2], r23[2];
                unpack2(acc2[i][0], r01[0], r01[1]);
                unpack2(acc2[i][1], r23[0], r23[1]);
                float rr[4] = {r01[0], r01[1], r23[0], r23[1]};
                float sp[4];
                unsigned bits = 0;
#pragma unroll
                for (int j = 0; j < 4; j++) {
                    float vn = __fadd_rn(__fmaf_rn(ALPHA, v[i * 4 + j], d[j]), rr[j]);
                    float s = (vn >= 1.0f) ? 1.0f : 0.0f;
                    v[i * 4 + j] = (vn >= 1.0f) ? 0.0f : vn;
                    cnt[i * 4 + j] += s;
                    sp[j] = s;
                    bits |= (s != 0.f) ? (1u << j) : 0u;
                }
                *(float4*)&s_next[(size_t)(b0 + rb) * NRES + j0 + cl0] =
                    make_float4(sp[0], sp[1], sp[2], sp[3]);

                unsigned partial = bits << (cl0 & 31);
                unsigned grp = 0xFFu << ((lane >> 3) << 3);
                unsigned word = __reduce_or_sync(grp, partial);
                if ((lane & 7) == 0)
                    g_mask[nbuf][b0 + rb][(j0 >> 5) + (lane >> 3)] = word;
            }

            grid_barrier();
        }
        grid_barrier();

#pragma unroll
        for (int i = 0; i < 2; i++) {
            float c0, c1, c2, c3;
            c0 = cnt[i * 4 + 0]; c1 = cnt[i * 4 + 1];
            c2 = cnt[i * 4 + 2]; c3 = cnt[i * 4 + 3];
            *(float4*)&out[(size_t)NB * NCLS +
                           (size_t)(b0 + rl0 + i) * NRES + j0 + cl0] =
                make_float4(c0, c1, c2, c3);
        }
    } else {
        // ---------------- Classifier path (numerics frozen) ----------------
        const bool active = tid < 256;
        const int idx = (blk - 128) * 256 + tid;
        const int b = idx / NCLS;
        const int m = idx % NCLS;
        float vc = 0.f, cc = 0.f;

        grid_barrier();

        for (int t = 0; t <= NT; ++t) {
            if (t >= 1 && active) {
                const float* __restrict__ s_prev = g_s[t & 1];
                const float* srow = &s_prev[(size_t)b * NRES];
                const float* wrow = &Wclf[(size_t)m * NRES];
                float tot = 0.f;
#pragma unroll
                for (int blkk = 0; blkk < 4; ++blkk) {
                    float a = 0.f;
#pragma unroll 8
                    for (int n = 0; n < 256; n += 4) {
                        int base = blkk * 256 + n;
                        float4 sv = __ldcg((const float4*)(srow + base));
                        float4 wv = *(const float4*)(wrow + base);
                        a = __fmaf_rn(sv.x, wv.x, a);
                        a = __fmaf_rn(sv.y, wv.y, a);
                        a = __fmaf_rn(sv.z, wv.z, a);
                        a = __fmaf_rn(sv.w, wv.w, a);
                    }
                    tot = __fadd_rn(tot, a);
                }
                float vn = __fmaf_rn(ALPHA, vc, tot);
                float s = (vn >= 1.0f) ? 1.0f : 0.0f;
                vc = (vn >= 1.0f) ? 0.0f : vn;
                cc += s;
            }
            grid_barrier();
        }
        if (active) out[idx] = cc;
    }
}

extern "C" void kernel_launch(void* const* d_in, const int* in_sizes, int n_in,
                              void* d_out, int out_size) {
    const float* x = 0; const float* Win = 0;
    const float* Wres = 0; const float* Wclf = 0;
    for (int i = 0; i < n_in; ++i) {
        switch (in_sizes[i]) {
            case NB * NC * NT:   x    = (const float*)d_in[i]; break;
            case NRES * NC:      Win  = (const float*)d_in[i]; break;
            case NRES * NRES:    Wres = (const float*)d_in[i]; break;
            case NCLS * NRES:    Wclf = (const float*)d_in[i]; break;
        }
    }
    float* out = (float*)d_out;

    cudaFuncSetAttribute(reservoir_persistent,
                         cudaFuncAttributeMaxDynamicSharedMemorySize, SMEM_TOTAL);
    reservoir_persistent<<<NBLK, NTHR, SMEM_TOTAL>>>(x, Win, Wres, Wclf, out);
}